// round 9
// baseline (speedup 1.0000x reference)
#include <cuda_runtime.h>
#include <math.h>

#define NB    1024
#define EMB   400
#define WW    20
#define FHW   18
#define FSZ   324
#define RN    96
#define RELF  864
#define NSET  6
#define NREL  500
#define EPSf  1e-5f

// ---------------- scratch ----------------------------------------------------
__device__ int   d_cnt[NREL];
__device__ float d_rp[RELF * 5 * 2];                 // krstat partials
__device__ float d_sc[RELF], d_sf[RELF];
__device__ float d_part[NSET * NB * 2];
__device__ float d_PQ[(size_t)NSET * NB * 54];
__device__ float d_ab[NSET * 2];
__device__ float d_p2[576 * 256 * 2];
__device__ float d_ss[NSET * RN * 2];
__device__ float d_soft[(size_t)NSET * NB * FSZ];

struct EPtrs { const int* e[NSET]; };

// ---------------- helpers ----------------------------------------------------
__device__ __forceinline__ float warp_sum(float v) {
#pragma unroll
    for (int o = 16; o > 0; o >>= 1) v += __shfl_down_sync(0xffffffffu, v, o);
    return v;
}
__device__ __forceinline__ float hsum16(float v) {
#pragma unroll
    for (int o = 8; o > 0; o >>= 1) v += __shfl_down_sync(0xffffffffu, v, o, 16);
    return v;
}
__device__ __forceinline__ unsigned long long pk2(float lo, float hi) {
    unsigned long long r;
    asm("mov.b64 %0,{%1,%2};" : "=l"(r) : "f"(lo), "f"(hi));
    return r;
}
__device__ __forceinline__ void upk2(unsigned long long v, float& lo, float& hi) {
    asm("mov.b64 {%0,%1},%2;" : "=f"(lo), "=f"(hi) : "l"(v));
}
__device__ __forceinline__ unsigned long long add2(unsigned long long a, unsigned long long b) {
    unsigned long long d;
    asm("add.rn.f32x2 %0,%1,%2;" : "=l"(d) : "l"(a), "l"(b));
    return d;
}
__device__ __forceinline__ unsigned long long fma2(unsigned long long a, unsigned long long b, unsigned long long c) {
    unsigned long long d;
    asm("fma.rn.f32x2 %0,%1,%2,%3;" : "=l"(d) : "l"(a), "l"(b), "l"(c));
    return d;
}

// ---------------- relation BN stats (histogram, 2-phase) ---------------------
__global__ void khist(const int* __restrict__ r_idx) {
    __shared__ int h[NREL];
    int t = threadIdx.x;
    if (t < NREL) h[t] = 0;
    __syncthreads();
    atomicAdd(&h[r_idx[t]], 1);
    __syncthreads();
    if (t < NREL) d_cnt[t] = h[t];
}

// grid (7, 5), 128 threads: partial count-weighted sums over 100 relations.
__global__ void krstatA(const float* __restrict__ R) {
    __shared__ float cf[100];
    int t = threadIdx.x, by = blockIdx.y;
    int rel0 = by * 100;
    if (t < 100) cf[t] = (rel0 + t < NREL) ? (float)d_cnt[rel0 + t] : 0.f;
    __syncthreads();
    int f = blockIdx.x * 128 + t;
    if (f >= RELF) return;
    float s = 0.f, s2 = 0.f;
#pragma unroll 4
    for (int i = 0; i < 100; i++) {
        float v = R[(size_t)(rel0 + i) * RELF + f];
        float c = cf[i];
        s  = fmaf(c, v, s);
        s2 = fmaf(c * v, v, s2);
    }
    d_rp[(f * 5 + by) * 2 + 0] = s;
    d_rp[(f * 5 + by) * 2 + 1] = s2;
}

__global__ void krstatB(const float* __restrict__ g2, const float* __restrict__ b2) {
    int f = blockIdx.x * 128 + threadIdx.x;
    if (f >= RELF) return;
    float s = 0.f, s2 = 0.f;
#pragma unroll
    for (int i = 0; i < 5; i++) {
        s  += d_rp[(f * 5 + i) * 2 + 0];
        s2 += d_rp[(f * 5 + i) * 2 + 1];
    }
    float m   = s * (1.f / NB);
    float var = s2 * (1.f / NB) - m * m;
    float sc  = rsqrtf(var + EPSf) * g2[f];
    d_sc[f] = sc;
    d_sf[f] = b2[f] - m * sc;
}

// ---------------- kstats1: 16 lanes per sample, 2 samples/warp ---------------
__global__ void __launch_bounds__(256) kstats1(EPtrs ep, const float* __restrict__ E) {
    int t = threadIdx.x;
    int wid = t >> 5, lane = t & 31;
    int g = lane >> 4, l16 = lane & 15;
    __shared__ float simg[16][400];
    int sid0 = blockIdx.x * 16 + wid * 2;

#pragma unroll
    for (int ss = 0; ss < 2; ss++) {
        int sid2 = sid0 + ss;
        int set2 = sid2 >> 10, b2 = sid2 & 1023;
        int eid2 = ep.e[set2][b2];
        float s = 0.f, s2 = 0.f;
        for (int i = lane; i < EMB; i += 32) {
            float v = E[(size_t)eid2 * EMB + i];
            simg[wid * 2 + ss][i] = v;
            s += v; s2 += v * v;
        }
        s = warp_sum(s); s2 = warp_sum(s2);
        if (lane == 0) { d_part[sid2 * 2] = s; d_part[sid2 * 2 + 1] = s2; }
    }
    __syncwarp();

    int sid = sid0 + g;
    const float* img = simg[wid * 2 + g];
    float aP[9], aQ[45];
#pragma unroll
    for (int i = 0; i < 9; i++)  aP[i] = 0.f;
#pragma unroll
    for (int i = 0; i < 45; i++) aQ[i] = 0.f;

    int pos = l16, y = 0, x = l16;
    while (pos < FSZ) {
        const float* row0 = &img[y * WW + x];
        float p[9];
#pragma unroll
        for (int dy = 0; dy < 3; dy++)
#pragma unroll
            for (int dx = 0; dx < 3; dx++)
                p[dy * 3 + dx] = row0[dy * WW + dx];
        int q = 0;
#pragma unroll
        for (int k1 = 0; k1 < 9; k1++) {
            aP[k1] += p[k1];
#pragma unroll
            for (int k2 = k1; k2 < 9; k2++) { aQ[q] = fmaf(p[k1], p[k2], aQ[q]); q++; }
        }
        pos += 16; x += 16;
        if (x >= FHW) { x -= FHW; y += 1; }
    }
#pragma unroll
    for (int c = 0; c < 9; c++)  aP[c] = hsum16(aP[c]);
#pragma unroll
    for (int c = 0; c < 45; c++) aQ[c] = hsum16(aQ[c]);
    if (l16 == 0) {
        size_t base = (size_t)sid * 54;
#pragma unroll
        for (int c = 0; c < 9; c++)  d_PQ[base + c] = aP[c];
#pragma unroll
        for (int c = 0; c < 45; c++) d_PQ[base + 9 + c] = aQ[c];
    }
}

// ---------------- kreduce0: BN0 alpha/beta -----------------------------------
__global__ void kreduce0(const float* __restrict__ g0, const float* __restrict__ b0) {
    int set = blockIdx.x, t = threadIdx.x;
    float s = 0.f, s2 = 0.f;
    for (int b = t; b < NB; b += 256) {
        s  += d_part[(set * NB + b) * 2 + 0];
        s2 += d_part[(set * NB + b) * 2 + 1];
    }
    float ws = warp_sum(s), ws2 = warp_sum(s2);
    __shared__ float sh[8][2];
    int wid = t >> 5, lane = t & 31;
    if (lane == 0) { sh[wid][0] = ws; sh[wid][1] = ws2; }
    __syncthreads();
    if (t == 0) {
        float S = 0.f, S2 = 0.f;
#pragma unroll
        for (int w = 0; w < 8; w++) { S += sh[w][0]; S2 += sh[w][1]; }
        const float inv = 1.f / ((float)NB * EMB);
        float m   = S * inv;
        float var = S2 * inv - m * m;
        float a   = g0[0] * rsqrtf(var + EPSf);
        d_ab[set * 2 + 0] = a;
        d_ab[set * 2 + 1] = b0[0] - m * a;
    }
}

// ---------------- kstats2a: b-major partials, rhat on the fly ----------------
// grid = 256 blocks (4 samples each), 576 threads.
__global__ void __launch_bounds__(576) kstats2a(const int* __restrict__ r_idx,
                                                const float* __restrict__ R) {
    __shared__ float s_rh[RELF];
    __shared__ float s_pq[NSET * 54];
    int t = threadIdx.x;
    int set = t / RN, r = t - set * RN;
    float alpha = d_ab[set * 2 + 0], beta = d_ab[set * 2 + 1];
    float S1 = 0.f, S2 = 0.f;
    for (int bi = 0; bi < 4; bi++) {
        int b = blockIdx.x * 4 + bi;
        size_t rbase = (size_t)r_idx[b] * RELF;
        __syncthreads();
        for (int i = t; i < RELF; i += 576)
            s_rh[i] = fmaf(R[rbase + i], d_sc[i], d_sf[i]);
        for (int i = t; i < NSET * 54; i += 576) {
            int s_ = i / 54, j = i - s_ * 54;
            s_pq[i] = d_PQ[((size_t)s_ * NB + b) * 54 + j];
        }
        __syncthreads();
        const float* pq = &s_pq[set * 54];
        const float* rh = &s_rh[r * 9];
        float rhv[9], Srh = 0.f, SrP = 0.f;
#pragma unroll
        for (int k = 0; k < 9; k++) {
            rhv[k] = rh[k];
            Srh += rhv[k];
            SrP += rhv[k] * pq[k];
        }
        float quad = 0.f;
        int q = 0;
#pragma unroll
        for (int k1 = 0; k1 < 9; k1++) {
            quad += rhv[k1] * rhv[k1] * pq[9 + q]; q++;
#pragma unroll
            for (int k2 = k1 + 1; k2 < 9; k2++) {
                quad += 2.f * rhv[k1] * rhv[k2] * pq[9 + q]; q++;
            }
        }
        float mC = alpha * SrP + (float)FSZ * beta * Srh;
        float x2 = alpha * alpha * quad
                 + 2.f * alpha * beta * Srh * SrP
                 + (float)FSZ * beta * beta * Srh * Srh;
        S1 += mC;
        S2 += x2;
    }
    d_p2[(t * 256 + blockIdx.x) * 2 + 0] = S1;
    d_p2[(t * 256 + blockIdx.x) * 2 + 1] = S2;
}

// grid = 576, 256 threads.
__global__ void kstats2b(const float* __restrict__ g1, const float* __restrict__ b1) {
    int c = blockIdx.x, t = threadIdx.x;
    int set = c / RN, r = c - set * RN;
    float v1 = d_p2[(c * 256 + t) * 2 + 0];
    float v2 = d_p2[(c * 256 + t) * 2 + 1];
    float w1 = warp_sum(v1), w2 = warp_sum(v2);
    __shared__ float sh[8][2];
    int wid = t >> 5, lane = t & 31;
    if (lane == 0) { sh[wid][0] = w1; sh[wid][1] = w2; }
    __syncthreads();
    if (t == 0) {
        float A = 0.f, B = 0.f;
#pragma unroll
        for (int w = 0; w < 8; w++) { A += sh[w][0]; B += sh[w][1]; }
        const float inv = 1.f / ((float)NB * FSZ);
        float m   = A * inv;
        float var = B * inv - m * m;
        float sc  = g1[r] * rsqrtf(var + EPSf);
        d_ss[(set * RN + r) * 2 + 0] = sc;
        d_ss[(set * RN + r) * 2 + 1] = b1[r] - m * sc;
    }
}

// ---------------- kmain v4 ---------------------------------------------------
// grid = (1024, 6), 256 threads = 8 warps. Warp w: channel group (w&3)*24,
// position group (w>>2)*162. Each lane: 6 consecutive positions = 3 f32x2 packs.
#define TKM 256
__global__ void __launch_bounds__(TKM) kmain(EPtrs ep, const float* __restrict__ E,
                                             const int* __restrict__ r_idx,
                                             const float* __restrict__ R) {
    int set = blockIdx.y, b = blockIdx.x, t = threadIdx.x;
    int wid = t >> 5, lane = t & 31;
    int chg = wid & 3, pg = wid >> 2;
    __shared__ float img[EMB];
    __shared__ __align__(16) float2 rw[RN * 10];    // 9 {sc*w} pairs + {sh} pair per ch
    __shared__ float ssc[RN];
    __shared__ __align__(16) float2 red[8][27][3];
    __shared__ float smax[2], ssum[2];

    int eid = ep.e[set][b];
    size_t rbase = (size_t)r_idx[b] * RELF;
    float alpha = d_ab[set * 2 + 0], beta = d_ab[set * 2 + 1];

    // phase A: gather relation row (BN2 applied on the fly), scales, image
    float vreg[4];
#pragma unroll
    for (int j = 0; j < 4; j++) {
        int i = t + j * TKM;
        vreg[j] = (i < RELF) ? fmaf(R[rbase + i], d_sc[i], d_sf[i]) : 0.f;
    }
    float mysh = 0.f;
    if (t < RN) {
        ssc[t] = d_ss[(set * RN + t) * 2 + 0];
        mysh   = d_ss[(set * RN + t) * 2 + 1];
    }
    for (int i = t; i < EMB; i += TKM)
        img[i] = fmaf(E[(size_t)eid * EMB + i], alpha, beta);
    __syncthreads();

    // phase B: scale-folded duplicated weight pairs
#pragma unroll
    for (int j = 0; j < 4; j++) {
        int i = t + j * TKM;
        if (i < RELF) {
            int r = i / 9, k = i - r * 9;
            float w = vreg[j] * ssc[r];
            rw[r * 10 + k] = make_float2(w, w);
        }
    }
    if (t < RN) rw[t * 10 + 9] = make_float2(mysh, mysh);
    __syncthreads();

    // phase C: 6 consecutive positions per lane as 3 packs
    int l = (lane < 27) ? lane : 26;
    int pbase = pg * 162 + 6 * l;
    unsigned long long P[3][9];
#pragma unroll
    for (int j = 0; j < 3; j++) {
        int p0 = pbase + 2 * j, p1 = p0 + 1;
        int y0 = p0 / FHW, x0 = p0 - y0 * FHW;
        int y1 = p1 / FHW, x1 = p1 - y1 * FHW;
#pragma unroll
        for (int dy = 0; dy < 3; dy++)
#pragma unroll
            for (int dx = 0; dx < 3; dx++)
                P[j][dy * 3 + dx] = pk2(img[(y0 + dy) * WW + x0 + dx],
                                        img[(y1 + dy) * WW + x1 + dx]);
    }

    const unsigned long long ABSM = 0x7fffffff7fffffffULL;
    unsigned long long S[3];
#pragma unroll
    for (int j = 0; j < 3; j++) S[j] = 0ull;
    const ulonglong2* rwq = (const ulonglong2*)rw;  // 5 x 16B per channel
    int r0 = chg * 24;
#pragma unroll 3
    for (int rr = 0; rr < 24; rr++) {
        int r = r0 + rr;
        ulonglong2 q0 = rwq[r * 5 + 0];
        ulonglong2 q1 = rwq[r * 5 + 1];
        ulonglong2 q2 = rwq[r * 5 + 2];
        ulonglong2 q3 = rwq[r * 5 + 3];
        ulonglong2 q4 = rwq[r * 5 + 4];   // w8, shift
#pragma unroll
        for (int j = 0; j < 3; j++) {
            unsigned long long a = fma2(P[j][0], q0.x, q4.y);
            a = fma2(P[j][1], q0.y, a);  a = fma2(P[j][2], q1.x, a);
            a = fma2(P[j][3], q1.y, a);  a = fma2(P[j][4], q2.x, a);
            a = fma2(P[j][5], q2.y, a);  a = fma2(P[j][6], q3.x, a);
            a = fma2(P[j][7], q3.y, a);  a = fma2(P[j][8], q4.x, a);
            S[j] = add2(S[j], add2(a, a & ABSM));   // += y + |y| = 2*relu(y)
        }
    }
    if (lane < 27) {
#pragma unroll
        for (int j = 0; j < 3; j++) {
            float lo, hi; upk2(S[j], lo, hi);
            red[wid][lane][j] = make_float2(lo, hi);
        }
    }
    __syncthreads();

    // reduction + softmax: warps 0 and 1 each handle one position group
    bool redw = (wid < 2);
    bool act = redw && (lane < 27);
    float v[6];
    const float NEGINF = __int_as_float(0xff800000u);
    float lm = NEGINF;
    if (redw) {
        int ll = (lane < 27) ? lane : 26;
#pragma unroll
        for (int j = 0; j < 3; j++) {
            float2 a0 = red[wid * 4 + 0][ll][j], a1 = red[wid * 4 + 1][ll][j];
            float2 a2 = red[wid * 4 + 2][ll][j], a3 = red[wid * 4 + 3][ll][j];
            v[2 * j]     = 0.5f * ((a0.x + a1.x) + (a2.x + a3.x));
            v[2 * j + 1] = 0.5f * ((a0.y + a1.y) + (a2.y + a3.y));
        }
        if (act) {
#pragma unroll
            for (int j = 0; j < 6; j++) lm = fmaxf(lm, v[j]);
        }
#pragma unroll
        for (int o = 16; o > 0; o >>= 1)
            lm = fmaxf(lm, __shfl_xor_sync(0xffffffffu, lm, o));
        if (lane == 0) smax[wid] = lm;
    }
    __syncthreads();
    float bm = fmaxf(smax[0], smax[1]);
    float e[6], ls = 0.f;
    if (redw) {
        if (act) {
#pragma unroll
            for (int j = 0; j < 6; j++) { e[j] = __expf(v[j] - bm); ls += e[j]; }
        }
#pragma unroll
        for (int o = 16; o > 0; o >>= 1)
            ls += __shfl_xor_sync(0xffffffffu, ls, o);
        if (lane == 0) ssum[wid] = ls;
    }
    __syncthreads();
    if (act) {
        float tot = ssum[0] + ssum[1];
        float* dst = &d_soft[((size_t)set * NB + b) * FSZ + wid * 162 + 6 * lane];
        if (eid == 0) {
            const float u = 1.f / (float)FSZ;
#pragma unroll
            for (int j = 0; j < 3; j++)
                *(float2*)&dst[2 * j] = make_float2(u, u);
        } else {
            float inv = 1.f / tot;
#pragma unroll
            for (int j = 0; j < 3; j++)
                *(float2*)&dst[2 * j] = make_float2(e[2 * j] * inv, e[2 * j + 1] * inv);
        }
    }
}

// ---------------- kfinal -----------------------------------------------------
__global__ void kfinal(const float* __restrict__ p, float* __restrict__ out) {
    int b = blockIdx.x, t = threadIdx.x;
    float acc = 0.f;
    for (int pos = t; pos < FSZ; pos += 128) {
        float prod = d_soft[((size_t)0 * NB + b) * FSZ + pos];
#pragma unroll
        for (int s = 1; s < NSET; s++)
            prod *= d_soft[((size_t)s * NB + b) * FSZ + pos];
        acc = fmaf(prod, p[pos], acc);
    }
    float ws = warp_sum(acc);
    __shared__ float sw[4];
    if ((t & 31) == 0) sw[t >> 5] = ws;
    __syncthreads();
    if (t == 0) out[b] = sw[0] + sw[1] + sw[2] + sw[3];
}

// ---------------- launcher ---------------------------------------------------
extern "C" void kernel_launch(void* const* d_in, const int* in_sizes, int n_in,
                              void* d_out, int out_size) {
    const int* r_idx = (const int*)d_in[0];
    EPtrs ep;
    for (int i = 0; i < NSET; i++) ep.e[i] = (const int*)d_in[1 + i];
    const float* E  = (const float*)d_in[7];
    const float* R  = (const float*)d_in[8];
    const float* g0 = (const float*)d_in[9];
    const float* b0 = (const float*)d_in[10];
    const float* g1 = (const float*)d_in[11];
    const float* b1 = (const float*)d_in[12];
    const float* g2 = (const float*)d_in[13];
    const float* b2 = (const float*)d_in[14];
    const float* p  = (const float*)d_in[15];
    float* out = (float*)d_out;

    khist   <<<1, NB>>>(r_idx);
    krstatA <<<dim3(7, 5), 128>>>(R);
    krstatB <<<7, 128>>>(g2, b2);
    kstats1 <<<384, 256>>>(ep, E);
    kreduce0<<<NSET, 256>>>(g0, b0);
    kstats2a<<<256, 576>>>(r_idx, R);
    kstats2b<<<576, 256>>>(g1, b1);
    kmain   <<<dim3(NB, NSET), TKM>>>(ep, E, r_idx, R);
    kfinal  <<<NB, 128>>>(p, out);
}

// round 10
// speedup vs baseline: 1.1125x; 1.1125x over previous
#include <cuda_runtime.h>
#include <math.h>

#define NB    1024
#define EMB   400
#define WW    20
#define FHW   18
#define FSZ   324
#define RN    96
#define RELF  864
#define NSET  6
#define NREL  500
#define EPSf  1e-5f

// ---------------- scratch ----------------------------------------------------
__device__ float d_rhat[(size_t)NB * RELF];
__device__ int   d_cnt[NREL];
__device__ float d_rp[RELF * 5 * 2];                 // krstat partials
__device__ float d_sc[RELF], d_sf[RELF];
__device__ float d_part[NSET * NB * 2];
__device__ float d_PQ[(size_t)NSET * NB * 54];
__device__ float d_ab[NSET * 2];
__device__ float d_p2[576 * 128 * 2];
__device__ float d_ss[NSET * RN * 2];
__device__ float d_soft[(size_t)NSET * NB * FSZ];

struct EPtrs { const int* e[NSET]; };

// ---------------- helpers ----------------------------------------------------
__device__ __forceinline__ float warp_sum(float v) {
#pragma unroll
    for (int o = 16; o > 0; o >>= 1) v += __shfl_down_sync(0xffffffffu, v, o);
    return v;
}
__device__ __forceinline__ float hsum16(float v) {
#pragma unroll
    for (int o = 8; o > 0; o >>= 1) v += __shfl_down_sync(0xffffffffu, v, o, 16);
    return v;
}
__device__ __forceinline__ unsigned long long pk2(float lo, float hi) {
    unsigned long long r;
    asm("mov.b64 %0,{%1,%2};" : "=l"(r) : "f"(lo), "f"(hi));
    return r;
}
__device__ __forceinline__ void upk2(unsigned long long v, float& lo, float& hi) {
    asm("mov.b64 {%0,%1},%2;" : "=f"(lo), "=f"(hi) : "l"(v));
}
__device__ __forceinline__ unsigned long long add2(unsigned long long a, unsigned long long b) {
    unsigned long long d;
    asm("add.rn.f32x2 %0,%1,%2;" : "=l"(d) : "l"(a), "l"(b));
    return d;
}
__device__ __forceinline__ unsigned long long fma2(unsigned long long a, unsigned long long b, unsigned long long c) {
    unsigned long long d;
    asm("fma.rn.f32x2 %0,%1,%2,%3;" : "=l"(d) : "l"(a), "l"(b), "l"(c));
    return d;
}

// ---------------- relation BN stats (histogram, 2-phase) ---------------------
__global__ void khist(const int* __restrict__ r_idx) {
    __shared__ int h[NREL];
    int t = threadIdx.x;
    if (t < NREL) h[t] = 0;
    __syncthreads();
    atomicAdd(&h[r_idx[t]], 1);
    __syncthreads();
    if (t < NREL) d_cnt[t] = h[t];
}

// grid (7, 5), 128 threads: partial count-weighted sums over 100 relations.
__global__ void krstatA(const float* __restrict__ R) {
    __shared__ float cf[100];
    int t = threadIdx.x, by = blockIdx.y;
    int rel0 = by * 100;
    if (t < 100) cf[t] = (rel0 + t < NREL) ? (float)d_cnt[rel0 + t] : 0.f;
    __syncthreads();
    int f = blockIdx.x * 128 + t;
    if (f >= RELF) return;
    float s = 0.f, s2 = 0.f;
#pragma unroll 4
    for (int i = 0; i < 100; i++) {
        float v = R[(size_t)(rel0 + i) * RELF + f];
        float c = cf[i];
        s  = fmaf(c, v, s);
        s2 = fmaf(c * v, v, s2);
    }
    d_rp[(f * 5 + by) * 2 + 0] = s;
    d_rp[(f * 5 + by) * 2 + 1] = s2;
}

__global__ void krstatB(const float* __restrict__ g2, const float* __restrict__ b2) {
    int f = blockIdx.x * 128 + threadIdx.x;
    if (f >= RELF) return;
    float s = 0.f, s2 = 0.f;
#pragma unroll
    for (int i = 0; i < 5; i++) {
        s  += d_rp[(f * 5 + i) * 2 + 0];
        s2 += d_rp[(f * 5 + i) * 2 + 1];
    }
    float m   = s * (1.f / NB);
    float var = s2 * (1.f / NB) - m * m;
    float sc  = rsqrtf(var + EPSf) * g2[f];
    d_sc[f] = sc;
    d_sf[f] = b2[f] - m * sc;
}

__global__ void kapply(const int* __restrict__ r_idx, const float* __restrict__ R) {
    int b = blockIdx.x, t = threadIdx.x;
    size_t base = (size_t)r_idx[b] * RELF;
    for (int i = t; i < RELF; i += 256)
        d_rhat[(size_t)b * RELF + i] = fmaf(R[base + i], d_sc[i], d_sf[i]);
}

// ---------------- kstats1: 16 lanes per sample, 2 samples/warp ---------------
// grid = 384 blocks, 256 threads; block = 16 samples.
__global__ void __launch_bounds__(256) kstats1(EPtrs ep, const float* __restrict__ E) {
    int t = threadIdx.x;
    int wid = t >> 5, lane = t & 31;
    int g = lane >> 4, l16 = lane & 15;
    __shared__ float simg[16][400];
    int sid0 = blockIdx.x * 16 + wid * 2;

#pragma unroll
    for (int ss = 0; ss < 2; ss++) {
        int sid2 = sid0 + ss;
        int set2 = sid2 >> 10, b2 = sid2 & 1023;
        int eid2 = ep.e[set2][b2];
        float s = 0.f, s2 = 0.f;
        for (int i = lane; i < EMB; i += 32) {
            float v = E[(size_t)eid2 * EMB + i];
            simg[wid * 2 + ss][i] = v;
            s += v; s2 += v * v;
        }
        s = warp_sum(s); s2 = warp_sum(s2);
        if (lane == 0) { d_part[sid2 * 2] = s; d_part[sid2 * 2 + 1] = s2; }
    }
    __syncwarp();

    int sid = sid0 + g;
    const float* img = simg[wid * 2 + g];
    float aP[9], aQ[45];
#pragma unroll
    for (int i = 0; i < 9; i++)  aP[i] = 0.f;
#pragma unroll
    for (int i = 0; i < 45; i++) aQ[i] = 0.f;

    int pos = l16, y = 0, x = l16;
    while (pos < FSZ) {
        const float* row0 = &img[y * WW + x];
        float p[9];
#pragma unroll
        for (int dy = 0; dy < 3; dy++)
#pragma unroll
            for (int dx = 0; dx < 3; dx++)
                p[dy * 3 + dx] = row0[dy * WW + dx];
        int q = 0;
#pragma unroll
        for (int k1 = 0; k1 < 9; k1++) {
            aP[k1] += p[k1];
#pragma unroll
            for (int k2 = k1; k2 < 9; k2++) { aQ[q] = fmaf(p[k1], p[k2], aQ[q]); q++; }
        }
        pos += 16; x += 16;
        if (x >= FHW) { x -= FHW; y += 1; }
    }
#pragma unroll
    for (int c = 0; c < 9; c++)  aP[c] = hsum16(aP[c]);
#pragma unroll
    for (int c = 0; c < 45; c++) aQ[c] = hsum16(aQ[c]);
    if (l16 == 0) {
        size_t base = (size_t)sid * 54;
#pragma unroll
        for (int c = 0; c < 9; c++)  d_PQ[base + c] = aP[c];
#pragma unroll
        for (int c = 0; c < 45; c++) d_PQ[base + 9 + c] = aQ[c];
    }
}

// ---------------- kreduce0: BN0 alpha/beta -----------------------------------
__global__ void kreduce0(const float* __restrict__ g0, const float* __restrict__ b0) {
    int set = blockIdx.x, t = threadIdx.x;
    float s = 0.f, s2 = 0.f;
    for (int b = t; b < NB; b += 256) {
        s  += d_part[(set * NB + b) * 2 + 0];
        s2 += d_part[(set * NB + b) * 2 + 1];
    }
    float ws = warp_sum(s), ws2 = warp_sum(s2);
    __shared__ float sh[8][2];
    int wid = t >> 5, lane = t & 31;
    if (lane == 0) { sh[wid][0] = ws; sh[wid][1] = ws2; }
    __syncthreads();
    if (t == 0) {
        float S = 0.f, S2 = 0.f;
#pragma unroll
        for (int w = 0; w < 8; w++) { S += sh[w][0]; S2 += sh[w][1]; }
        const float inv = 1.f / ((float)NB * EMB);
        float m   = S * inv;
        float var = S2 * inv - m * m;
        float a   = g0[0] * rsqrtf(var + EPSf);
        d_ab[set * 2 + 0] = a;
        d_ab[set * 2 + 1] = b0[0] - m * a;
    }
}

// ---------------- kstats2a: b-major partials (smem reuse) --------------------
__global__ void __launch_bounds__(576) kstats2a() {
    __shared__ float s_rh[RELF];
    __shared__ float s_pq[NSET * 54];
    int t = threadIdx.x;
    int set = t / RN, r = t - set * RN;
    float alpha = d_ab[set * 2 + 0], beta = d_ab[set * 2 + 1];
    float S1 = 0.f, S2 = 0.f;
    for (int bi = 0; bi < 8; bi++) {
        int b = blockIdx.x * 8 + bi;
        __syncthreads();
        for (int i = t; i < RELF; i += 576) s_rh[i] = d_rhat[(size_t)b * RELF + i];
        for (int i = t; i < NSET * 54; i += 576) {
            int s_ = i / 54, j = i - s_ * 54;
            s_pq[i] = d_PQ[((size_t)s_ * NB + b) * 54 + j];
        }
        __syncthreads();
        const float* pq = &s_pq[set * 54];
        const float* rh = &s_rh[r * 9];
        float rhv[9], Srh = 0.f, SrP = 0.f;
#pragma unroll
        for (int k = 0; k < 9; k++) {
            rhv[k] = rh[k];
            Srh += rhv[k];
            SrP += rhv[k] * pq[k];
        }
        float quad = 0.f;
        int q = 0;
#pragma unroll
        for (int k1 = 0; k1 < 9; k1++) {
            quad += rhv[k1] * rhv[k1] * pq[9 + q]; q++;
#pragma unroll
            for (int k2 = k1 + 1; k2 < 9; k2++) {
                quad += 2.f * rhv[k1] * rhv[k2] * pq[9 + q]; q++;
            }
        }
        float mC = alpha * SrP + (float)FSZ * beta * Srh;
        float x2 = alpha * alpha * quad
                 + 2.f * alpha * beta * Srh * SrP
                 + (float)FSZ * beta * beta * Srh * Srh;
        S1 += mC;
        S2 += x2;
    }
    d_p2[(t * 128 + blockIdx.x) * 2 + 0] = S1;
    d_p2[(t * 128 + blockIdx.x) * 2 + 1] = S2;
}

__global__ void kstats2b(const float* __restrict__ g1, const float* __restrict__ b1) {
    int c = blockIdx.x, t = threadIdx.x;
    int set = c / RN, r = c - set * RN;
    float v1 = d_p2[(c * 128 + t) * 2 + 0];
    float v2 = d_p2[(c * 128 + t) * 2 + 1];
    float w1 = warp_sum(v1), w2 = warp_sum(v2);
    __shared__ float sh[4][2];
    int wid = t >> 5, lane = t & 31;
    if (lane == 0) { sh[wid][0] = w1; sh[wid][1] = w2; }
    __syncthreads();
    if (t == 0) {
        float A = sh[0][0] + sh[1][0] + sh[2][0] + sh[3][0];
        float B = sh[0][1] + sh[1][1] + sh[2][1] + sh[3][1];
        const float inv = 1.f / ((float)NB * FSZ);
        float m   = A * inv;
        float var = B * inv - m * m;
        float sc  = g1[r] * rsqrtf(var + EPSf);
        d_ss[(set * RN + r) * 2 + 0] = sc;
        d_ss[(set * RN + r) * 2 + 1] = b1[r] - m * sc;
    }
}

// ---------------- kmain v3 ---------------------------------------------------
// grid = (1024, 6), 128 threads = 4 warps; warp w handles channels [24w, 24w+24),
// each lane holds 12 consecutive positions as 54 packed f32x2 registers.
#define TKM 128
__global__ void __launch_bounds__(TKM) kmain(EPtrs ep, const float* __restrict__ E) {
    int set = blockIdx.y, b = blockIdx.x, t = threadIdx.x;
    int wid = t >> 5, lane = t & 31;
    __shared__ float img[EMB];
    __shared__ __align__(16) float2 rw[RN * 10];    // per ch: 9 {sc*w} pairs + {sh} pair
    __shared__ float ssc[RN];
    __shared__ __align__(16) float2 red[4][32][6];

    int eid = ep.e[set][b];
    float alpha = d_ab[set * 2 + 0], beta = d_ab[set * 2 + 1];

    // phase A: raw weights to regs, scale/shift to smem/regs, normalized image
    float vreg[7];
#pragma unroll
    for (int j = 0; j < 7; j++) {
        int i = t + j * TKM;
        vreg[j] = (i < RELF) ? d_rhat[(size_t)b * RELF + i] : 0.f;
    }
    float mysh = 0.f;
    if (t < RN) {
        ssc[t] = d_ss[(set * RN + t) * 2 + 0];
        mysh   = d_ss[(set * RN + t) * 2 + 1];
    }
    for (int i = t; i < EMB; i += TKM)
        img[i] = fmaf(E[(size_t)eid * EMB + i], alpha, beta);
    __syncthreads();

    // phase B: scale-folded duplicated weight pairs
#pragma unroll
    for (int j = 0; j < 7; j++) {
        int i = t + j * TKM;
        if (i < RELF) {
            int r = i / 9, k = i - r * 9;
            float w = vreg[j] * ssc[r];
            rw[r * 10 + k] = make_float2(w, w);
        }
    }
    if (t < RN) rw[t * 10 + 9] = make_float2(mysh, mysh);
    __syncthreads();

    // phase C: 12 consecutive positions per lane into packed registers
    int l = (lane < 27) ? lane : 26;
    unsigned long long P[6][9];
    {
        int base = 12 * l;
#pragma unroll
        for (int j = 0; j < 6; j++) {
            int p0 = base + 2 * j, p1 = p0 + 1;
            int y0 = p0 / FHW, x0 = p0 - y0 * FHW;
            int y1 = p1 / FHW, x1 = p1 - y1 * FHW;
#pragma unroll
            for (int dy = 0; dy < 3; dy++)
#pragma unroll
                for (int dx = 0; dx < 3; dx++)
                    P[j][dy * 3 + dx] = pk2(img[(y0 + dy) * WW + x0 + dx],
                                            img[(y1 + dy) * WW + x1 + dx]);
        }
    }

    const unsigned long long ABSM = 0x7fffffff7fffffffULL;
    unsigned long long S[6];
#pragma unroll
    for (int j = 0; j < 6; j++) S[j] = 0ull;
    const ulonglong2* rwq = (const ulonglong2*)rw;  // 5 x 16B per channel
    int r0 = wid * 24;
#pragma unroll 2
    for (int rr = 0; rr < 24; rr++) {
        int r = r0 + rr;
        ulonglong2 q0 = rwq[r * 5 + 0];
        ulonglong2 q1 = rwq[r * 5 + 1];
        ulonglong2 q2 = rwq[r * 5 + 2];
        ulonglong2 q3 = rwq[r * 5 + 3];
        ulonglong2 q4 = rwq[r * 5 + 4];   // w8, shift
#pragma unroll
        for (int j = 0; j < 6; j++) {
            unsigned long long a = fma2(P[j][0], q0.x, q4.y);
            a = fma2(P[j][1], q0.y, a);  a = fma2(P[j][2], q1.x, a);
            a = fma2(P[j][3], q1.y, a);  a = fma2(P[j][4], q2.x, a);
            a = fma2(P[j][5], q2.y, a);  a = fma2(P[j][6], q3.x, a);
            a = fma2(P[j][7], q3.y, a);  a = fma2(P[j][8], q4.x, a);
            S[j] = add2(S[j], add2(a, a & ABSM));   // += y + |y| = 2*relu(y)
        }
    }
#pragma unroll
    for (int j = 0; j < 6; j++) {
        float lo, hi; upk2(S[j], lo, hi);
        red[wid][lane][j] = make_float2(lo, hi);
    }
    __syncthreads();

    if (wid == 0) {
        float v[12];
#pragma unroll
        for (int j = 0; j < 6; j++) {
            float2 a0 = red[0][lane][j], a1 = red[1][lane][j];
            float2 a2 = red[2][lane][j], a3 = red[3][lane][j];
            v[2 * j]     = 0.5f * ((a0.x + a1.x) + (a2.x + a3.x));
            v[2 * j + 1] = 0.5f * ((a0.y + a1.y) + (a2.y + a3.y));
        }
        bool act = lane < 27;
        const float NEGINF = __int_as_float(0xff800000u);
        float lm = NEGINF;
        if (act) {
#pragma unroll
            for (int j = 0; j < 12; j++) lm = fmaxf(lm, v[j]);
        }
#pragma unroll
        for (int o = 16; o > 0; o >>= 1)
            lm = fmaxf(lm, __shfl_xor_sync(0xffffffffu, lm, o));
        float e[12], ls = 0.f;
        if (act) {
#pragma unroll
            for (int j = 0; j < 12; j++) { e[j] = __expf(v[j] - lm); ls += e[j]; }
        }
#pragma unroll
        for (int o = 16; o > 0; o >>= 1)
            ls += __shfl_xor_sync(0xffffffffu, ls, o);
        if (act) {
            float* dst = &d_soft[((size_t)set * NB + b) * FSZ + 12 * lane];
            if (eid == 0) {
                const float u = 1.f / (float)FSZ;
#pragma unroll
                for (int j = 0; j < 3; j++)
                    *(float4*)&dst[4 * j] = make_float4(u, u, u, u);
            } else {
                float inv = 1.f / ls;
#pragma unroll
                for (int j = 0; j < 3; j++)
                    *(float4*)&dst[4 * j] = make_float4(e[4*j] * inv, e[4*j+1] * inv,
                                                        e[4*j+2] * inv, e[4*j+3] * inv);
            }
        }
    }
}

// ---------------- kfinal -----------------------------------------------------
__global__ void kfinal(const float* __restrict__ p, float* __restrict__ out) {
    int b = blockIdx.x, t = threadIdx.x;
    float acc = 0.f;
    for (int pos = t; pos < FSZ; pos += 128) {
        float prod = d_soft[((size_t)0 * NB + b) * FSZ + pos];
#pragma unroll
        for (int s = 1; s < NSET; s++)
            prod *= d_soft[((size_t)s * NB + b) * FSZ + pos];
        acc = fmaf(prod, p[pos], acc);
    }
    float ws = warp_sum(acc);
    __shared__ float sw[4];
    if ((t & 31) == 0) sw[t >> 5] = ws;
    __syncthreads();
    if (t == 0) out[b] = sw[0] + sw[1] + sw[2] + sw[3];
}

// ---------------- launcher ---------------------------------------------------
extern "C" void kernel_launch(void* const* d_in, const int* in_sizes, int n_in,
                              void* d_out, int out_size) {
    const int* r_idx = (const int*)d_in[0];
    EPtrs ep;
    for (int i = 0; i < NSET; i++) ep.e[i] = (const int*)d_in[1 + i];
    const float* E  = (const float*)d_in[7];
    const float* R  = (const float*)d_in[8];
    const float* g0 = (const float*)d_in[9];
    const float* b0 = (const float*)d_in[10];
    const float* g1 = (const float*)d_in[11];
    const float* b1 = (const float*)d_in[12];
    const float* g2 = (const float*)d_in[13];
    const float* b2 = (const float*)d_in[14];
    const float* p  = (const float*)d_in[15];
    float* out = (float*)d_out;

    khist   <<<1, NB>>>(r_idx);
    krstatA <<<dim3(7, 5), 128>>>(R);
    krstatB <<<7, 128>>>(g2, b2);
    kapply  <<<NB, 256>>>(r_idx, R);
    kstats1 <<<384, 256>>>(ep, E);
    kreduce0<<<NSET, 256>>>(g0, b0);
    kstats2a<<<128, 576>>>();
    kstats2b<<<576, 128>>>(g1, b1);
    kmain   <<<dim3(NB, NSET), TKM>>>(ep, E);
    kfinal  <<<NB, 128>>>(p, out);
}

// round 12
// speedup vs baseline: 1.1703x; 1.0520x over previous
#include <cuda_runtime.h>
#include <math.h>

#define NB    1024
#define EMB   400
#define WW    20
#define FHW   18
#define FSZ   324
#define RN    96
#define RELF  864
#define NSET  6
#define NREL  500
#define EPSf  1e-5f

// ---------------- scratch ----------------------------------------------------
__device__ float d_rhat[(size_t)NB * RELF];
__device__ float d_rp[RELF * 5 * 2];                 // krstat partials
__device__ float d_sc[RELF], d_sf[RELF];
__device__ float d_part[NSET * NB * 2];
__device__ float d_PQ[(size_t)NSET * NB * 54];
__device__ float d_ab[NSET * 2];
__device__ float d_p2[576 * 128 * 2];
__device__ float d_ss[NSET * RN * 2];
__device__ float d_soft[(size_t)NSET * NB * FSZ];

struct EPtrs { const int* e[NSET]; };

// ---------------- helpers ----------------------------------------------------
__device__ __forceinline__ float warp_sum(float v) {
#pragma unroll
    for (int o = 16; o > 0; o >>= 1) v += __shfl_down_sync(0xffffffffu, v, o);
    return v;
}
__device__ __forceinline__ float hsum16(float v) {
#pragma unroll
    for (int o = 8; o > 0; o >>= 1) v += __shfl_down_sync(0xffffffffu, v, o, 16);
    return v;
}
__device__ __forceinline__ unsigned long long pk2(float lo, float hi) {
    unsigned long long r;
    asm("mov.b64 %0,{%1,%2};" : "=l"(r) : "f"(lo), "f"(hi));
    return r;
}
__device__ __forceinline__ void upk2(unsigned long long v, float& lo, float& hi) {
    asm("mov.b64 {%0,%1},%2;" : "=f"(lo), "=f"(hi) : "l"(v));
}
__device__ __forceinline__ unsigned long long add2(unsigned long long a, unsigned long long b) {
    unsigned long long d;
    asm("add.rn.f32x2 %0,%1,%2;" : "=l"(d) : "l"(a), "l"(b));
    return d;
}
__device__ __forceinline__ unsigned long long fma2(unsigned long long a, unsigned long long b, unsigned long long c) {
    unsigned long long d;
    asm("fma.rn.f32x2 %0,%1,%2,%3;" : "=l"(d) : "l"(a), "l"(b), "l"(c));
    return d;
}

// ---------------- kfront1: fused kstats1 (blocks 0..383) + krstatA (384..403)
// 256 threads everywhere.
__global__ void __launch_bounds__(256) kfront1(EPtrs ep, const float* __restrict__ E,
                                               const int* __restrict__ r_idx,
                                               const float* __restrict__ R) {
    int bx = blockIdx.x;
    int t = threadIdx.x;

    if (bx >= 384) {
        // ---- krstatA role: histogram-fused relation partial stats ----
        __shared__ int   h[100];
        __shared__ float cf[100];
        int idx = bx - 384;           // 0..19
        int by  = idx >> 2;           // relation slice 0..4
        int fx  = idx & 3;            // feature chunk 0..3
        int rel0 = by * 100;
        if (t < 100) h[t] = 0;
        __syncthreads();
        for (int i = t; i < NB; i += 256) {
            int rv = r_idx[i] - rel0;
            if (rv >= 0 && rv < 100) atomicAdd(&h[rv], 1);
        }
        __syncthreads();
        if (t < 100) cf[t] = (float)h[t];
        __syncthreads();
        int f = fx * 256 + t;
        if (f >= RELF) return;
        float s = 0.f, s2 = 0.f;
#pragma unroll 4
        for (int i = 0; i < 100; i++) {
            float v = R[(size_t)(rel0 + i) * RELF + f];
            float c = cf[i];
            s  = fmaf(c, v, s);
            s2 = fmaf(c * v, v, s2);
        }
        d_rp[(f * 5 + by) * 2 + 0] = s;
        d_rp[(f * 5 + by) * 2 + 1] = s2;
        return;
    }

    // ---- kstats1 role: 16 lanes per sample, 2 samples/warp ----
    int wid = t >> 5, lane = t & 31;
    int g = lane >> 4, l16 = lane & 15;
    __shared__ float simg[16][400];
    int sid0 = bx * 16 + wid * 2;

#pragma unroll
    for (int ss = 0; ss < 2; ss++) {
        int sid2 = sid0 + ss;
        int set2 = sid2 >> 10, b2 = sid2 & 1023;
        int eid2 = ep.e[set2][b2];
        float s = 0.f, s2 = 0.f;
        for (int i = lane; i < EMB; i += 32) {
            float v = E[(size_t)eid2 * EMB + i];
            simg[wid * 2 + ss][i] = v;
            s += v; s2 += v * v;
        }
        s = warp_sum(s); s2 = warp_sum(s2);
        if (lane == 0) { d_part[sid2 * 2] = s; d_part[sid2 * 2 + 1] = s2; }
    }
    __syncwarp();

    int sid = sid0 + g;
    const float* img = simg[wid * 2 + g];
    float aP[9], aQ[45];
#pragma unroll
    for (int i = 0; i < 9; i++)  aP[i] = 0.f;
#pragma unroll
    for (int i = 0; i < 45; i++) aQ[i] = 0.f;

    int pos = l16, y = 0, x = l16;
    while (pos < FSZ) {
        const float* row0 = &img[y * WW + x];
        float p[9];
#pragma unroll
        for (int dy = 0; dy < 3; dy++)
#pragma unroll
            for (int dx = 0; dx < 3; dx++)
                p[dy * 3 + dx] = row0[dy * WW + dx];
        int q = 0;
#pragma unroll
        for (int k1 = 0; k1 < 9; k1++) {
            aP[k1] += p[k1];
#pragma unroll
            for (int k2 = k1; k2 < 9; k2++) { aQ[q] = fmaf(p[k1], p[k2], aQ[q]); q++; }
        }
        pos += 16; x += 16;
        if (x >= FHW) { x -= FHW; y += 1; }
    }
#pragma unroll
    for (int c = 0; c < 9; c++)  aP[c] = hsum16(aP[c]);
#pragma unroll
    for (int c = 0; c < 45; c++) aQ[c] = hsum16(aQ[c]);
    if (l16 == 0) {
        size_t base = (size_t)sid * 54;
#pragma unroll
        for (int c = 0; c < 9; c++)  d_PQ[base + c] = aP[c];
#pragma unroll
        for (int c = 0; c < 45; c++) d_PQ[base + 9 + c] = aQ[c];
    }
}

// ---------------- kfront2: fused krstatB (blocks 0..3) + kreduce0 (4..9) ----
__global__ void __launch_bounds__(256) kfront2(const float* __restrict__ g2,
                                               const float* __restrict__ b2,
                                               const float* __restrict__ g0,
                                               const float* __restrict__ b0) {
    int bx = blockIdx.x;
    int t = threadIdx.x;

    if (bx < 4) {
        // ---- krstatB role: combine relation partials -> sc/sf ----
        int f = bx * 256 + t;
        if (f >= RELF) return;
        float s = 0.f, s2 = 0.f;
#pragma unroll
        for (int i = 0; i < 5; i++) {
            s  += d_rp[(f * 5 + i) * 2 + 0];
            s2 += d_rp[(f * 5 + i) * 2 + 1];
        }
        float m   = s * (1.f / NB);
        float var = s2 * (1.f / NB) - m * m;
        float sc  = rsqrtf(var + EPSf) * g2[f];
        d_sc[f] = sc;
        d_sf[f] = b2[f] - m * sc;
        return;
    }

    // ---- kreduce0 role: BN0 alpha/beta ----
    int set = bx - 4;
    float s = 0.f, s2 = 0.f;
    for (int b = t; b < NB; b += 256) {
        s  += d_part[(set * NB + b) * 2 + 0];
        s2 += d_part[(set * NB + b) * 2 + 1];
    }
    float ws = warp_sum(s), ws2 = warp_sum(s2);
    __shared__ float sh[8][2];
    int wid = t >> 5, lane = t & 31;
    if (lane == 0) { sh[wid][0] = ws; sh[wid][1] = ws2; }
    __syncthreads();
    if (t == 0) {
        float S = 0.f, S2 = 0.f;
#pragma unroll
        for (int w = 0; w < 8; w++) { S += sh[w][0]; S2 += sh[w][1]; }
        const float inv = 1.f / ((float)NB * EMB);
        float m   = S * inv;
        float var = S2 * inv - m * m;
        float a   = g0[0] * rsqrtf(var + EPSf);
        d_ab[set * 2 + 0] = a;
        d_ab[set * 2 + 1] = b0[0] - m * a;
    }
}

// ---------------- kapply -----------------------------------------------------
__global__ void kapply(const int* __restrict__ r_idx, const float* __restrict__ R) {
    int b = blockIdx.x, t = threadIdx.x;
    size_t base = (size_t)r_idx[b] * RELF;
    for (int i = t; i < RELF; i += 256)
        d_rhat[(size_t)b * RELF + i] = fmaf(R[base + i], d_sc[i], d_sf[i]);
}

// ---------------- kstats2a: b-major partials (smem reuse) --------------------
__global__ void __launch_bounds__(576) kstats2a() {
    __shared__ float s_rh[RELF];
    __shared__ float s_pq[NSET * 54];
    int t = threadIdx.x;
    int set = t / RN, r = t - set * RN;
    float alpha = d_ab[set * 2 + 0], beta = d_ab[set * 2 + 1];
    float S1 = 0.f, S2 = 0.f;
    for (int bi = 0; bi < 8; bi++) {
        int b = blockIdx.x * 8 + bi;
        __syncthreads();
        for (int i = t; i < RELF; i += 576) s_rh[i] = d_rhat[(size_t)b * RELF + i];
        for (int i = t; i < NSET * 54; i += 576) {
            int s_ = i / 54, j = i - s_ * 54;
            s_pq[i] = d_PQ[((size_t)s_ * NB + b) * 54 + j];
        }
        __syncthreads();
        const float* pq = &s_pq[set * 54];
        const float* rh = &s_rh[r * 9];
        float rhv[9], Srh = 0.f, SrP = 0.f;
#pragma unroll
        for (int k = 0; k < 9; k++) {
            rhv[k] = rh[k];
            Srh += rhv[k];
            SrP += rhv[k] * pq[k];
        }
        float quad = 0.f;
        int q = 0;
#pragma unroll
        for (int k1 = 0; k1 < 9; k1++) {
            quad += rhv[k1] * rhv[k1] * pq[9 + q]; q++;
#pragma unroll
            for (int k2 = k1 + 1; k2 < 9; k2++) {
                quad += 2.f * rhv[k1] * rhv[k2] * pq[9 + q]; q++;
            }
        }
        float mC = alpha * SrP + (float)FSZ * beta * Srh;
        float x2 = alpha * alpha * quad
                 + 2.f * alpha * beta * Srh * SrP
                 + (float)FSZ * beta * beta * Srh * Srh;
        S1 += mC;
        S2 += x2;
    }
    d_p2[(t * 128 + blockIdx.x) * 2 + 0] = S1;
    d_p2[(t * 128 + blockIdx.x) * 2 + 1] = S2;
}

__global__ void kstats2b(const float* __restrict__ g1, const float* __restrict__ b1) {
    int c = blockIdx.x, t = threadIdx.x;
    int set = c / RN, r = c - set * RN;
    float v1 = d_p2[(c * 128 + t) * 2 + 0];
    float v2 = d_p2[(c * 128 + t) * 2 + 1];
    float w1 = warp_sum(v1), w2 = warp_sum(v2);
    __shared__ float sh[4][2];
    int wid = t >> 5, lane = t & 31;
    if (lane == 0) { sh[wid][0] = w1; sh[wid][1] = w2; }
    __syncthreads();
    if (t == 0) {
        float A = sh[0][0] + sh[1][0] + sh[2][0] + sh[3][0];
        float B = sh[0][1] + sh[1][1] + sh[2][1] + sh[3][1];
        const float inv = 1.f / ((float)NB * FSZ);
        float m   = A * inv;
        float var = B * inv - m * m;
        float sc  = g1[r] * rsqrtf(var + EPSf);
        d_ss[(set * RN + r) * 2 + 0] = sc;
        d_ss[(set * RN + r) * 2 + 1] = b1[r] - m * sc;
    }
}

// ---------------- kmain v3 (unchanged, proven) -------------------------------
#define TKM 128
__global__ void __launch_bounds__(TKM) kmain(EPtrs ep, const float* __restrict__ E) {
    int set = blockIdx.y, b = blockIdx.x, t = threadIdx.x;
    int wid = t >> 5, lane = t & 31;
    __shared__ float img[EMB];
    __shared__ __align__(16) float2 rw[RN * 10];
    __shared__ float ssc[RN];
    __shared__ __align__(16) float2 red[4][32][6];

    int eid = ep.e[set][b];
    float alpha = d_ab[set * 2 + 0], beta = d_ab[set * 2 + 1];

    float vreg[7];
#pragma unroll
    for (int j = 0; j < 7; j++) {
        int i = t + j * TKM;
        vreg[j] = (i < RELF) ? d_rhat[(size_t)b * RELF + i] : 0.f;
    }
    float mysh = 0.f;
    if (t < RN) {
        ssc[t] = d_ss[(set * RN + t) * 2 + 0];
        mysh   = d_ss[(set * RN + t) * 2 + 1];
    }
    for (int i = t; i < EMB; i += TKM)
        img[i] = fmaf(E[(size_t)eid * EMB + i], alpha, beta);
    __syncthreads();

#pragma unroll
    for (int j = 0; j < 7; j++) {
        int i = t + j * TKM;
        if (i < RELF) {
            int r = i / 9, k = i - r * 9;
            float w = vreg[j] * ssc[r];
            rw[r * 10 + k] = make_float2(w, w);
        }
    }
    if (t < RN) rw[t * 10 + 9] = make_float2(mysh, mysh);
    __syncthreads();

    int l = (lane < 27) ? lane : 26;
    unsigned long long P[6][9];
    {
        int base = 12 * l;
#pragma unroll
        for (int j = 0; j < 6; j++) {
            int p0 = base + 2 * j, p1 = p0 + 1;
            int y0 = p0 / FHW, x0 = p0 - y0 * FHW;
            int y1 = p1 / FHW, x1 = p1 - y1 * FHW;
#pragma unroll
            for (int dy = 0; dy < 3; dy++)
#pragma unroll
                for (int dx = 0; dx < 3; dx++)
                    P[j][dy * 3 + dx] = pk2(img[(y0 + dy) * WW + x0 + dx],
                                            img[(y1 + dy) * WW + x1 + dx]);
        }
    }

    const unsigned long long ABSM = 0x7fffffff7fffffffULL;
    unsigned long long S[6];
#pragma unroll
    for (int j = 0; j < 6; j++) S[j] = 0ull;
    const ulonglong2* rwq = (const ulonglong2*)rw;
    int r0 = wid * 24;
#pragma unroll 2
    for (int rr = 0; rr < 24; rr++) {
        int r = r0 + rr;
        ulonglong2 q0 = rwq[r * 5 + 0];
        ulonglong2 q1 = rwq[r * 5 + 1];
        ulonglong2 q2 = rwq[r * 5 + 2];
        ulonglong2 q3 = rwq[r * 5 + 3];
        ulonglong2 q4 = rwq[r * 5 + 4];
#pragma unroll
        for (int j = 0; j < 6; j++) {
            unsigned long long a = fma2(P[j][0], q0.x, q4.y);
            a = fma2(P[j][1], q0.y, a);  a = fma2(P[j][2], q1.x, a);
            a = fma2(P[j][3], q1.y, a);  a = fma2(P[j][4], q2.x, a);
            a = fma2(P[j][5], q2.y, a);  a = fma2(P[j][6], q3.x, a);
            a = fma2(P[j][7], q3.y, a);  a = fma2(P[j][8], q4.x, a);
            S[j] = add2(S[j], add2(a, a & ABSM));
        }
    }
#pragma unroll
    for (int j = 0; j < 6; j++) {
        float lo, hi; upk2(S[j], lo, hi);
        red[wid][lane][j] = make_float2(lo, hi);
    }
    __syncthreads();

    if (wid == 0) {
        float v[12];
#pragma unroll
        for (int j = 0; j < 6; j++) {
            float2 a0 = red[0][lane][j], a1 = red[1][lane][j];
            float2 a2 = red[2][lane][j], a3 = red[3][lane][j];
            v[2 * j]     = 0.5f * ((a0.x + a1.x) + (a2.x + a3.x));
            v[2 * j + 1] = 0.5f * ((a0.y + a1.y) + (a2.y + a3.y));
        }
        bool act = lane < 27;
        const float NEGINF = __int_as_float(0xff800000u);
        float lm = NEGINF;
        if (act) {
#pragma unroll
            for (int j = 0; j < 12; j++) lm = fmaxf(lm, v[j]);
        }
#pragma unroll
        for (int o = 16; o > 0; o >>= 1)
            lm = fmaxf(lm, __shfl_xor_sync(0xffffffffu, lm, o));
        float e[12], ls = 0.f;
        if (act) {
#pragma unroll
            for (int j = 0; j < 12; j++) { e[j] = __expf(v[j] - lm); ls += e[j]; }
        }
#pragma unroll
        for (int o = 16; o > 0; o >>= 1)
            ls += __shfl_xor_sync(0xffffffffu, ls, o);
        if (act) {
            float* dst = &d_soft[((size_t)set * NB + b) * FSZ + 12 * lane];
            if (eid == 0) {
                const float u = 1.f / (float)FSZ;
#pragma unroll
                for (int j = 0; j < 3; j++)
                    *(float4*)&dst[4 * j] = make_float4(u, u, u, u);
            } else {
                float inv = 1.f / ls;
#pragma unroll
                for (int j = 0; j < 3; j++)
                    *(float4*)&dst[4 * j] = make_float4(e[4*j] * inv, e[4*j+1] * inv,
                                                        e[4*j+2] * inv, e[4*j+3] * inv);
            }
        }
    }
}

// ---------------- kfinal -----------------------------------------------------
__global__ void kfinal(const float* __restrict__ p, float* __restrict__ out) {
    int b = blockIdx.x, t = threadIdx.x;
    float acc = 0.f;
    for (int pos = t; pos < FSZ; pos += 128) {
        float prod = d_soft[((size_t)0 * NB + b) * FSZ + pos];
#pragma unroll
        for (int s = 1; s < NSET; s++)
            prod *= d_soft[((size_t)s * NB + b) * FSZ + pos];
        acc = fmaf(prod, p[pos], acc);
    }
    float ws = warp_sum(acc);
    __shared__ float sw[4];
    if ((t & 31) == 0) sw[t >> 5] = ws;
    __syncthreads();
    if (t == 0) out[b] = sw[0] + sw[1] + sw[2] + sw[3];
}

// ---------------- launcher (single stream, capture-trivial) ------------------
extern "C" void kernel_launch(void* const* d_in, const int* in_sizes, int n_in,
                              void* d_out, int out_size) {
    const int* r_idx = (const int*)d_in[0];
    EPtrs ep;
    for (int i = 0; i < NSET; i++) ep.e[i] = (const int*)d_in[1 + i];
    const float* E  = (const float*)d_in[7];
    const float* R  = (const float*)d_in[8];
    const float* g0 = (const float*)d_in[9];
    const float* b0 = (const float*)d_in[10];
    const float* g1 = (const float*)d_in[11];
    const float* b1 = (const float*)d_in[12];
    const float* g2 = (const float*)d_in[13];
    const float* b2 = (const float*)d_in[14];
    const float* p  = (const float*)d_in[15];
    float* out = (float*)d_out;

    kfront1 <<<404, 256>>>(ep, E, r_idx, R);
    kfront2 <<<10, 256>>>(g2, b2, g0, b0);
    kapply  <<<NB, 256>>>(r_idx, R);
    kstats2a<<<128, 576>>>();
    kstats2b<<<576, 128>>>(g1, b1);
    kmain   <<<dim3(NB, NSET), TKM>>>(ep, E);
    kfinal  <<<NB, 128>>>(p, out);
}

// round 13
// speedup vs baseline: 1.2342x; 1.0546x over previous
#include <cuda_runtime.h>
#include <math.h>

#define NB    1024
#define EMB   400
#define WW    20
#define FHW   18
#define FSZ   324
#define RN    96
#define RELF  864
#define NSET  6
#define NREL  500
#define EPSf  1e-5f

// ---------------- scratch ----------------------------------------------------
__device__ float d_rhat[(size_t)NB * RELF];
__device__ float d_rp[RELF * 5 * 2];                 // krstat partials
__device__ float d_sc[RELF], d_sf[RELF];
__device__ float d_part[NSET * NB * 2];
__device__ float d_PQ[(size_t)NSET * NB * 54];
__device__ float d_ab[NSET * 2];
__device__ float d_p2[576 * 128 * 2];
__device__ float d_ss[NSET * RN * 2];
__device__ float d_soft[(size_t)NSET * NB * FSZ];

struct EPtrs { const int* e[NSET]; };

// ---------------- helpers ----------------------------------------------------
__device__ __forceinline__ float warp_sum(float v) {
#pragma unroll
    for (int o = 16; o > 0; o >>= 1) v += __shfl_down_sync(0xffffffffu, v, o);
    return v;
}
__device__ __forceinline__ float hsum16(float v) {
#pragma unroll
    for (int o = 8; o > 0; o >>= 1) v += __shfl_down_sync(0xffffffffu, v, o, 16);
    return v;
}
__device__ __forceinline__ unsigned long long pk2(float lo, float hi) {
    unsigned long long r;
    asm("mov.b64 %0,{%1,%2};" : "=l"(r) : "f"(lo), "f"(hi));
    return r;
}
__device__ __forceinline__ void upk2(unsigned long long v, float& lo, float& hi) {
    asm("mov.b64 {%0,%1},%2;" : "=f"(lo), "=f"(hi) : "l"(v));
}
__device__ __forceinline__ unsigned long long add2(unsigned long long a, unsigned long long b) {
    unsigned long long d;
    asm("add.rn.f32x2 %0,%1,%2;" : "=l"(d) : "l"(a), "l"(b));
    return d;
}
__device__ __forceinline__ unsigned long long fma2(unsigned long long a, unsigned long long b, unsigned long long c) {
    unsigned long long d;
    asm("fma.rn.f32x2 %0,%1,%2,%3;" : "=l"(d) : "l"(a), "l"(b), "l"(c));
    return d;
}

// ---------------- kfront1: fused kstats1 (blocks 0..383) + krstatA (384..403)
__global__ void __launch_bounds__(256) kfront1(EPtrs ep, const float* __restrict__ E,
                                               const int* __restrict__ r_idx,
                                               const float* __restrict__ R) {
    int bx = blockIdx.x;
    int t = threadIdx.x;

    if (bx >= 384) {
        // ---- krstatA role: histogram-fused relation partial stats ----
        __shared__ int   h[100];
        __shared__ float cf[100];
        int idx = bx - 384;           // 0..19
        int by  = idx >> 2;           // relation slice 0..4
        int fx  = idx & 3;            // feature chunk 0..3
        int rel0 = by * 100;
        if (t < 100) h[t] = 0;
        __syncthreads();
        for (int i = t; i < NB; i += 256) {
            int rv = r_idx[i] - rel0;
            if (rv >= 0 && rv < 100) atomicAdd(&h[rv], 1);
        }
        __syncthreads();
        if (t < 100) cf[t] = (float)h[t];
        __syncthreads();
        int f = fx * 256 + t;
        if (f >= RELF) return;
        float s = 0.f, s2 = 0.f;
#pragma unroll 4
        for (int i = 0; i < 100; i++) {
            float v = R[(size_t)(rel0 + i) * RELF + f];
            float c = cf[i];
            s  = fmaf(c, v, s);
            s2 = fmaf(c * v, v, s2);
        }
        d_rp[(f * 5 + by) * 2 + 0] = s;
        d_rp[(f * 5 + by) * 2 + 1] = s2;
        return;
    }

    // ---- kstats1 role: 16 lanes per sample, 2 samples/warp ----
    int wid = t >> 5, lane = t & 31;
    int g = lane >> 4, l16 = lane & 15;
    __shared__ float simg[16][400];
    int sid0 = bx * 16 + wid * 2;

#pragma unroll
    for (int ss = 0; ss < 2; ss++) {
        int sid2 = sid0 + ss;
        int set2 = sid2 >> 10, b2 = sid2 & 1023;
        int eid2 = ep.e[set2][b2];
        float s = 0.f, s2 = 0.f;
        for (int i = lane; i < EMB; i += 32) {
            float v = E[(size_t)eid2 * EMB + i];
            simg[wid * 2 + ss][i] = v;
            s += v; s2 += v * v;
        }
        s = warp_sum(s); s2 = warp_sum(s2);
        if (lane == 0) { d_part[sid2 * 2] = s; d_part[sid2 * 2 + 1] = s2; }
    }
    __syncwarp();

    int sid = sid0 + g;
    const float* img = simg[wid * 2 + g];
    float aP[9], aQ[45];
#pragma unroll
    for (int i = 0; i < 9; i++)  aP[i] = 0.f;
#pragma unroll
    for (int i = 0; i < 45; i++) aQ[i] = 0.f;

    int pos = l16, y = 0, x = l16;
    while (pos < FSZ) {
        const float* row0 = &img[y * WW + x];
        float p[9];
#pragma unroll
        for (int dy = 0; dy < 3; dy++)
#pragma unroll
            for (int dx = 0; dx < 3; dx++)
                p[dy * 3 + dx] = row0[dy * WW + dx];
        int q = 0;
#pragma unroll
        for (int k1 = 0; k1 < 9; k1++) {
            aP[k1] += p[k1];
#pragma unroll
            for (int k2 = k1; k2 < 9; k2++) { aQ[q] = fmaf(p[k1], p[k2], aQ[q]); q++; }
        }
        pos += 16; x += 16;
        if (x >= FHW) { x -= FHW; y += 1; }
    }
#pragma unroll
    for (int c = 0; c < 9; c++)  aP[c] = hsum16(aP[c]);
#pragma unroll
    for (int c = 0; c < 45; c++) aQ[c] = hsum16(aQ[c]);
    if (l16 == 0) {
        size_t base = (size_t)sid * 54;
#pragma unroll
        for (int c = 0; c < 9; c++)  d_PQ[base + c] = aP[c];
#pragma unroll
        for (int c = 0; c < 45; c++) d_PQ[base + 9 + c] = aQ[c];
    }
}

// ---------------- kfront2: fused krstatB (blocks 0..3) + kreduce0 (4..9) ----
__global__ void __launch_bounds__(256) kfront2(const float* __restrict__ g2,
                                               const float* __restrict__ b2,
                                               const float* __restrict__ g0,
                                               const float* __restrict__ b0) {
    int bx = blockIdx.x;
    int t = threadIdx.x;

    if (bx < 4) {
        int f = bx * 256 + t;
        if (f >= RELF) return;
        float s = 0.f, s2 = 0.f;
#pragma unroll
        for (int i = 0; i < 5; i++) {
            s  += d_rp[(f * 5 + i) * 2 + 0];
            s2 += d_rp[(f * 5 + i) * 2 + 1];
        }
        float m   = s * (1.f / NB);
        float var = s2 * (1.f / NB) - m * m;
        float sc  = rsqrtf(var + EPSf) * g2[f];
        d_sc[f] = sc;
        d_sf[f] = b2[f] - m * sc;
        return;
    }

    int set = bx - 4;
    float s = 0.f, s2 = 0.f;
    for (int b = t; b < NB; b += 256) {
        s  += d_part[(set * NB + b) * 2 + 0];
        s2 += d_part[(set * NB + b) * 2 + 1];
    }
    float ws = warp_sum(s), ws2 = warp_sum(s2);
    __shared__ float sh[8][2];
    int wid = t >> 5, lane = t & 31;
    if (lane == 0) { sh[wid][0] = ws; sh[wid][1] = ws2; }
    __syncthreads();
    if (t == 0) {
        float S = 0.f, S2 = 0.f;
#pragma unroll
        for (int w = 0; w < 8; w++) { S += sh[w][0]; S2 += sh[w][1]; }
        const float inv = 1.f / ((float)NB * EMB);
        float m   = S * inv;
        float var = S2 * inv - m * m;
        float a   = g0[0] * rsqrtf(var + EPSf);
        d_ab[set * 2 + 0] = a;
        d_ab[set * 2 + 1] = b0[0] - m * a;
    }
}

// ---------------- kstats2a v2: single load phase, rhat fused ----------------
// grid = 128 blocks (8 samples each), 576 threads. One barrier per block.
// Also materializes d_rhat for kmain (replaces the old kapply kernel).
__global__ void __launch_bounds__(576) kstats2a(const int* __restrict__ r_idx,
                                                const float* __restrict__ R) {
    __shared__ float s_rh[8][RELF];       // 27648 B
    __shared__ float s_pq[8][NSET * 54];  // 10368 B
    int t = threadIdx.x;
    int set = t / RN, r = t - set * RN;
    int b0 = blockIdx.x * 8;

    // stage all 8 samples: rhat computed on the fly from R + written out
    for (int i = t; i < 8 * RELF; i += 576) {
        int bi = i / RELF, j = i - bi * RELF;
        int b = b0 + bi;
        float v = fmaf(R[(size_t)r_idx[b] * RELF + j], d_sc[j], d_sf[j]);
        s_rh[bi][j] = v;
        d_rhat[(size_t)b * RELF + j] = v;
    }
    for (int i = t; i < 8 * NSET * 54; i += 576) {
        int bi = i / (NSET * 54), j = i - bi * (NSET * 54);
        int s_ = j / 54, k = j - s_ * 54;
        s_pq[bi][j] = d_PQ[((size_t)s_ * NB + (b0 + bi)) * 54 + k];
    }
    __syncthreads();

    float alpha = d_ab[set * 2 + 0], beta = d_ab[set * 2 + 1];
    float S1 = 0.f, S2 = 0.f;
#pragma unroll 2
    for (int bi = 0; bi < 8; bi++) {
        const float* pq = &s_pq[bi][set * 54];
        const float* rh = &s_rh[bi][r * 9];
        float rhv[9], Srh = 0.f, SrP = 0.f;
#pragma unroll
        for (int k = 0; k < 9; k++) {
            rhv[k] = rh[k];
            Srh += rhv[k];
            SrP += rhv[k] * pq[k];
        }
        float quad = 0.f;
        int q = 0;
#pragma unroll
        for (int k1 = 0; k1 < 9; k1++) {
            quad += rhv[k1] * rhv[k1] * pq[9 + q]; q++;
#pragma unroll
            for (int k2 = k1 + 1; k2 < 9; k2++) {
                quad += 2.f * rhv[k1] * rhv[k2] * pq[9 + q]; q++;
            }
        }
        float mC = alpha * SrP + (float)FSZ * beta * Srh;
        float x2 = alpha * alpha * quad
                 + 2.f * alpha * beta * Srh * SrP
                 + (float)FSZ * beta * beta * Srh * Srh;
        S1 += mC;
        S2 += x2;
    }
    d_p2[(t * 128 + blockIdx.x) * 2 + 0] = S1;
    d_p2[(t * 128 + blockIdx.x) * 2 + 1] = S2;
}

__global__ void kstats2b(const float* __restrict__ g1, const float* __restrict__ b1) {
    int c = blockIdx.x, t = threadIdx.x;
    int set = c / RN, r = c - set * RN;
    float v1 = d_p2[(c * 128 + t) * 2 + 0];
    float v2 = d_p2[(c * 128 + t) * 2 + 1];
    float w1 = warp_sum(v1), w2 = warp_sum(v2);
    __shared__ float sh[4][2];
    int wid = t >> 5, lane = t & 31;
    if (lane == 0) { sh[wid][0] = w1; sh[wid][1] = w2; }
    __syncthreads();
    if (t == 0) {
        float A = sh[0][0] + sh[1][0] + sh[2][0] + sh[3][0];
        float B = sh[0][1] + sh[1][1] + sh[2][1] + sh[3][1];
        const float inv = 1.f / ((float)NB * FSZ);
        float m   = A * inv;
        float var = B * inv - m * m;
        float sc  = g1[r] * rsqrtf(var + EPSf);
        d_ss[(set * RN + r) * 2 + 0] = sc;
        d_ss[(set * RN + r) * 2 + 1] = b1[r] - m * sc;
    }
}

// ---------------- kmain v3 (unchanged, proven) -------------------------------
#define TKM 128
__global__ void __launch_bounds__(TKM) kmain(EPtrs ep, const float* __restrict__ E) {
    int set = blockIdx.y, b = blockIdx.x, t = threadIdx.x;
    int wid = t >> 5, lane = t & 31;
    __shared__ float img[EMB];
    __shared__ __align__(16) float2 rw[RN * 10];
    __shared__ float ssc[RN];
    __shared__ __align__(16) float2 red[4][32][6];

    int eid = ep.e[set][b];
    float alpha = d_ab[set * 2 + 0], beta = d_ab[set * 2 + 1];

    float vreg[7];
#pragma unroll
    for (int j = 0; j < 7; j++) {
        int i = t + j * TKM;
        vreg[j] = (i < RELF) ? d_rhat[(size_t)b * RELF + i] : 0.f;
    }
    float mysh = 0.f;
    if (t < RN) {
        ssc[t] = d_ss[(set * RN + t) * 2 + 0];
        mysh   = d_ss[(set * RN + t) * 2 + 1];
    }
    for (int i = t; i < EMB; i += TKM)
        img[i] = fmaf(E[(size_t)eid * EMB + i], alpha, beta);
    __syncthreads();

#pragma unroll
    for (int j = 0; j < 7; j++) {
        int i = t + j * TKM;
        if (i < RELF) {
            int r = i / 9, k = i - r * 9;
            float w = vreg[j] * ssc[r];
            rw[r * 10 + k] = make_float2(w, w);
        }
    }
    if (t < RN) rw[t * 10 + 9] = make_float2(mysh, mysh);
    __syncthreads();

    int l = (lane < 27) ? lane : 26;
    unsigned long long P[6][9];
    {
        int base = 12 * l;
#pragma unroll
        for (int j = 0; j < 6; j++) {
            int p0 = base + 2 * j, p1 = p0 + 1;
            int y0 = p0 / FHW, x0 = p0 - y0 * FHW;
            int y1 = p1 / FHW, x1 = p1 - y1 * FHW;
#pragma unroll
            for (int dy = 0; dy < 3; dy++)
#pragma unroll
                for (int dx = 0; dx < 3; dx++)
                    P[j][dy * 3 + dx] = pk2(img[(y0 + dy) * WW + x0 + dx],
                                            img[(y1 + dy) * WW + x1 + dx]);
        }
    }

    const unsigned long long ABSM = 0x7fffffff7fffffffULL;
    unsigned long long S[6];
#pragma unroll
    for (int j = 0; j < 6; j++) S[j] = 0ull;
    const ulonglong2* rwq = (const ulonglong2*)rw;
    int r0 = wid * 24;
#pragma unroll 2
    for (int rr = 0; rr < 24; rr++) {
        int r = r0 + rr;
        ulonglong2 q0 = rwq[r * 5 + 0];
        ulonglong2 q1 = rwq[r * 5 + 1];
        ulonglong2 q2 = rwq[r * 5 + 2];
        ulonglong2 q3 = rwq[r * 5 + 3];
        ulonglong2 q4 = rwq[r * 5 + 4];
#pragma unroll
        for (int j = 0; j < 6; j++) {
            unsigned long long a = fma2(P[j][0], q0.x, q4.y);
            a = fma2(P[j][1], q0.y, a);  a = fma2(P[j][2], q1.x, a);
            a = fma2(P[j][3], q1.y, a);  a = fma2(P[j][4], q2.x, a);
            a = fma2(P[j][5], q2.y, a);  a = fma2(P[j][6], q3.x, a);
            a = fma2(P[j][7], q3.y, a);  a = fma2(P[j][8], q4.x, a);
            S[j] = add2(S[j], add2(a, a & ABSM));
        }
    }
#pragma unroll
    for (int j = 0; j < 6; j++) {
        float lo, hi; upk2(S[j], lo, hi);
        red[wid][lane][j] = make_float2(lo, hi);
    }
    __syncthreads();

    if (wid == 0) {
        float v[12];
#pragma unroll
        for (int j = 0; j < 6; j++) {
            float2 a0 = red[0][lane][j], a1 = red[1][lane][j];
            float2 a2 = red[2][lane][j], a3 = red[3][lane][j];
            v[2 * j]     = 0.5f * ((a0.x + a1.x) + (a2.x + a3.x));
            v[2 * j + 1] = 0.5f * ((a0.y + a1.y) + (a2.y + a3.y));
        }
        bool act = lane < 27;
        const float NEGINF = __int_as_float(0xff800000u);
        float lm = NEGINF;
        if (act) {
#pragma unroll
            for (int j = 0; j < 12; j++) lm = fmaxf(lm, v[j]);
        }
#pragma unroll
        for (int o = 16; o > 0; o >>= 1)
            lm = fmaxf(lm, __shfl_xor_sync(0xffffffffu, lm, o));
        float e[12], ls = 0.f;
        if (act) {
#pragma unroll
            for (int j = 0; j < 12; j++) { e[j] = __expf(v[j] - lm); ls += e[j]; }
        }
#pragma unroll
        for (int o = 16; o > 0; o >>= 1)
            ls += __shfl_xor_sync(0xffffffffu, ls, o);
        if (act) {
            float* dst = &d_soft[((size_t)set * NB + b) * FSZ + 12 * lane];
            if (eid == 0) {
                const float u = 1.f / (float)FSZ;
#pragma unroll
                for (int j = 0; j < 3; j++)
                    *(float4*)&dst[4 * j] = make_float4(u, u, u, u);
            } else {
                float inv = 1.f / ls;
#pragma unroll
                for (int j = 0; j < 3; j++)
                    *(float4*)&dst[4 * j] = make_float4(e[4*j] * inv, e[4*j+1] * inv,
                                                        e[4*j+2] * inv, e[4*j+3] * inv);
            }
        }
    }
}

// ---------------- kfinal -----------------------------------------------------
__global__ void kfinal(const float* __restrict__ p, float* __restrict__ out) {
    int b = blockIdx.x, t = threadIdx.x;
    float acc = 0.f;
    for (int pos = t; pos < FSZ; pos += 128) {
        float prod = d_soft[((size_t)0 * NB + b) * FSZ + pos];
#pragma unroll
        for (int s = 1; s < NSET; s++)
            prod *= d_soft[((size_t)s * NB + b) * FSZ + pos];
        acc = fmaf(prod, p[pos], acc);
    }
    float ws = warp_sum(acc);
    __shared__ float sw[4];
    if ((t & 31) == 0) sw[t >> 5] = ws;
    __syncthreads();
    if (t == 0) out[b] = sw[0] + sw[1] + sw[2] + sw[3];
}

// ---------------- launcher (single stream, capture-trivial) ------------------
extern "C" void kernel_launch(void* const* d_in, const int* in_sizes, int n_in,
                              void* d_out, int out_size) {
    const int* r_idx = (const int*)d_in[0];
    EPtrs ep;
    for (int i = 0; i < NSET; i++) ep.e[i] = (const int*)d_in[1 + i];
    const float* E  = (const float*)d_in[7];
    const float* R  = (const float*)d_in[8];
    const float* g0 = (const float*)d_in[9];
    const float* b0 = (const float*)d_in[10];
    const float* g1 = (const float*)d_in[11];
    const float* b1 = (const float*)d_in[12];
    const float* g2 = (const float*)d_in[13];
    const float* b2 = (const float*)d_in[14];
    const float* p  = (const float*)d_in[15];
    float* out = (float*)d_out;

    kfront1 <<<404, 256>>>(ep, E, r_idx, R);
    kfront2 <<<10, 256>>>(g2, b2, g0, b0);
    kstats2a<<<128, 576>>>(r_idx, R);
    kstats2b<<<576, 128>>>(g1, b1);
    kmain   <<<dim3(NB, NSET), TKM>>>(ep, E);
    kfinal  <<<NB, 128>>>(p, out);
}